// round 9
// baseline (speedup 1.0000x reference)
#include <cuda_runtime.h>
#include <cuda_fp16.h>
#include <cstdint>

#define BATCH 32768
#define NCH   256
#define FLAT  3072
#define NRED  152
#define NBLK_MOM 128
#define EPSV  1e-5f

// ---------------- device scratch ----------------
__device__ float g_part[NBLK_MOM][NRED];
__device__ float g_wscaled[NCH * 16];
__device__ float g_shift[NCH];
// fc1 weights fp16 (hi only), layout [k'][n], k' = p*256 + c
__device__ __half g_w1hi[FLAT * 128];

// ======================= PTX helpers ==================
__device__ __forceinline__ uint32_t smem_u32(const void* p) {
    uint32_t a;
    asm("{ .reg .u64 t; cvta.to.shared.u64 t, %1; cvt.u32.u64 %0, t; }"
        : "=r"(a) : "l"(p));
    return a;
}
#define CP_ASYNC16(dst, src) \
    asm volatile("cp.async.cg.shared.global [%0], [%1], 16;" \
        :: "r"(dst), "l"(src) : "memory")
#define CP_COMMIT() asm volatile("cp.async.commit_group;" ::: "memory")
#define CP_WAIT1()  asm volatile("cp.async.wait_group 1;" ::: "memory")
#define CP_WAIT0()  asm volatile("cp.async.wait_group 0;" ::: "memory")

__device__ __forceinline__ void ldsm_x4t(uint32_t r[4], uint32_t addr) {
    asm volatile("ldmatrix.sync.aligned.m8n8.x4.trans.shared.b16 {%0,%1,%2,%3}, [%4];"
        : "=r"(r[0]), "=r"(r[1]), "=r"(r[2]), "=r"(r[3]) : "r"(addr));
}
__device__ __forceinline__ void mma16816(float& d0, float& d1, float& d2, float& d3,
                                         uint32_t a0, uint32_t a1, uint32_t a2, uint32_t a3,
                                         uint32_t b0, uint32_t b1) {
    asm volatile(
        "mma.sync.aligned.m16n8k16.row.col.f32.f16.f16.f32 "
        "{%0,%1,%2,%3}, {%4,%5,%6,%7}, {%8,%9}, {%0,%1,%2,%3};"
        : "+f"(d0), "+f"(d1), "+f"(d2), "+f"(d3)
        : "r"(a0), "r"(a1), "r"(a2), "r"(a3), "r"(b0), "r"(b1));
}
__device__ __forceinline__ uint32_t f2h2(float a, float b) {
    __half2 h = __floats2half2_rn(a, b);
    return *reinterpret_cast<uint32_t*>(&h);
}

// =========================================================================
// K1: patch moments (proven)
// =========================================================================
__global__ void k_moments(const float* __restrict__ x)
{
    int b = blockIdx.x * 256 + threadIdx.x;
    const float* xb = x + b * 42;
    float xv[42];
#pragma unroll
    for (int i = 0; i < 42; i++) xv[i] = xb[i];

    __shared__ float red[8][NRED];
    int lane = threadIdx.x & 31;
    int warp = threadIdx.x >> 5;

    int idx = 0;
#pragma unroll
    for (int k = 0; k < 16; k++) {
        float s = 0.f;
#pragma unroll
        for (int r = 0; r < 3; r++)
#pragma unroll
            for (int c = 0; c < 4; c++)
                s += xv[(r + (k >> 2)) * 7 + (c + (k & 3))];
#pragma unroll
        for (int o = 16; o; o >>= 1) s += __shfl_xor_sync(0xffffffffu, s, o);
        if (lane == 0) red[warp][idx] = s;
        idx++;
    }
#pragma unroll
    for (int k = 0; k < 16; k++) {
#pragma unroll
        for (int l = k; l < 16; l++) {
            float s = 0.f;
#pragma unroll
            for (int r = 0; r < 3; r++)
#pragma unroll
                for (int c = 0; c < 4; c++)
                    s += xv[(r + (k >> 2)) * 7 + (c + (k & 3))] *
                         xv[(r + (l >> 2)) * 7 + (c + (l & 3))];
#pragma unroll
            for (int o = 16; o; o >>= 1) s += __shfl_xor_sync(0xffffffffu, s, o);
            if (lane == 0) red[warp][idx] = s;
            idx++;
        }
    }
    __syncthreads();
    if (threadIdx.x < NRED) {
        float s = 0.f;
#pragma unroll
        for (int w = 0; w < 8; w++) s += red[w][threadIdx.x];
        g_part[blockIdx.x][threadIdx.x] = s;
    }
}

// =========================================================================
// K2: finalize BN fold (proven)
// =========================================================================
__global__ void k_finalize(const float* __restrict__ conv_w,
                           const float* __restrict__ bn_gamma,
                           const float* __restrict__ bn_beta)
{
    __shared__ float S[NRED];
    int t = threadIdx.x;
    if (t < NRED) {
        float s = 0.f;
        for (int bl = 0; bl < NBLK_MOM; bl++) s += g_part[bl][t];
        S[t] = s * (1.f / (12.f * (float)BATCH));
    }
    __syncthreads();
    if (t < NCH) {
        float w[16];
#pragma unroll
        for (int i = 0; i < 16; i++) w[i] = conv_w[t * 16 + i];
        float mraw = 0.f;
#pragma unroll
        for (int i = 0; i < 16; i++) mraw += w[i] * S[i];
        float q = 0.f;
        int idx = 16;
#pragma unroll
        for (int k = 0; k < 16; k++)
#pragma unroll
            for (int l = k; l < 16; l++) {
                float coef = (k == l) ? (w[k] * w[l]) : (2.f * w[k] * w[l]);
                q += coef * S[idx];
                idx++;
            }
        float var = q - mraw * mraw;
        float a = bn_gamma[t] * rsqrtf(var + EPSV);
#pragma unroll
        for (int i = 0; i < 16; i++) g_wscaled[t * 16 + i] = a * w[i];
        g_shift[t] = bn_beta[t] - a * mraw;
    }
}

// =========================================================================
// K_prep: W1 -> [k'][n] fp16 (hi only).  kp = p*256+c, f = c*12+p.
// =========================================================================
__global__ void k_prep(const float* __restrict__ pw1, const float* __restrict__ vw1)
{
    int kp = blockIdx.x;
    int n  = threadIdx.x;
    int p = kp >> 8, c = kp & 255;
    int f = c * 12 + p;
    float v = (n < 64) ? pw1[(size_t)f * 64 + n] : vw1[(size_t)f * 64 + (n - 64)];
    g_w1hi[(size_t)kp * 128 + n] = __float2half_rn(v);
}

// =========================================================================
// K4: software-pipelined register-dataflow kernel.
// Groups g = 0..95 (32 channels each). Per group step:
//   pack(g): cd -> afr          (conv(g) results long since landed)
//   conv(g+1): 2 LDSM + 4 MMA -> cd   (independent; hides behind fc1)
//   fc1(g): 16 MMA with interleaved B loads
// Smem: B ring 3x16384 @0 | Wc hi @49152 | shift @57344
//       epilogue reuse: h1 [128][129] f32 @0, h2 [128][65] @66560
// =========================================================================
#define NITER    48
#define OFF_B    0
#define OFF_WC   49152
#define OFF_SH   57344
#define SMEM_DYN 99840

__global__ __launch_bounds__(256, 2) void k_fused(
    const float* __restrict__ x,
    const float* __restrict__ pb1, const float* __restrict__ vb1,
    const float* __restrict__ pw2, const float* __restrict__ pb2,
    const float* __restrict__ pw3, const float* __restrict__ pb3,
    const float* __restrict__ vw2, const float* __restrict__ vb2,
    const float* __restrict__ vw3, const float* __restrict__ vb3,
    float* __restrict__ out)
{
    extern __shared__ char dyn_pool[];
    __shared__ float biasS[128];

    char* poolA = dyn_pool;
    const uint32_t pool_u = smem_u32(poolA);

    const int tid  = threadIdx.x;
    const int wid  = tid >> 5;
    const int lane = tid & 31;
    const int m0   = blockIdx.x * 128;

    float* shiftS = (float*)(poolA + OFF_SH);

    // ---- one-time smem fills ----
    if (tid < 64)       biasS[tid] = pb1[tid];
    else if (tid < 128) biasS[tid] = vb1[tid - 64];
    {   // folded conv weights -> Wc[k][c] fp16 (hi), swizzled rows of 512B
#pragma unroll
        for (int i = 0; i < 16; i++) {
            int idx = tid + i * 256;
            int k = idx >> 8, c = idx & 255;
            float v = g_wscaled[c * 16 + k];
            uint32_t o = (uint32_t)k * 512 + ((((uint32_t)(c >> 3)) ^ (k & 7)) << 4) + (c & 7) * 2;
            *(__half*)(poolA + OFF_WC + o) = __float2half_rn(v);
        }
    }
    shiftS[tid] = g_shift[tid];

    // ---- fc1 B cp.async lanes ----
    const int brow = tid >> 2;
    const int bq   = (tid & 3) * 4;
    const __half* gB = g_w1hi + (size_t)brow * 128 + bq * 8;
    uint32_t oBs[4];
#pragma unroll
    for (int j = 0; j < 4; j++)
        oBs[j] = (uint32_t)brow * 256 + ((((uint32_t)(bq + j)) ^ (brow & 7)) << 4);

    // ---- prologue B(0), B(1) ----
#pragma unroll
    for (int pc = 0; pc < 2; pc++) {
        const uint32_t sb = pool_u + OFF_B + pc * 16384;
        const size_t kofs = (size_t)pc * 64 * 128;
#pragma unroll
        for (int j = 0; j < 4; j++)
            CP_ASYNC16(sb + oBs[j], gB + kofs + j * 8);
        CP_COMMIT();
    }

    // ---- lane constants ----
    const int g    = lane >> 2;
    const int t2   = (lane & 3) * 2;
    const int b_kl = ((lane >> 3) & 1) * 8 + (lane & 7);
    const int b_ng = (lane >> 4);
    const uint32_t key = (uint32_t)(b_kl & 7);
    const int xo0 = ((t2 >> 2) * 7 + (t2 & 3));
    const int xo1 = (((t2 + 8) >> 2) * 7 + ((t2 + 8) & 3));

    // D accumulators: m16 x n128 per warp
    float d[16][4];
#pragma unroll
    for (int nt = 0; nt < 16; nt++)
#pragma unroll
        for (int q = 0; q < 4; q++) d[nt][q] = 0.f;

    __syncthreads();   // Wc / shift visible

    uint32_t xhi[4];   // x fragments (per patch)
    float cd[4][4];    // in-flight conv results for group "g2" (next to pack)

    // conv issue for group g2 (0..95): rebuild x-frags at patch boundary,
    // 2 LDSM + 4 independent MMAs into cd.
    auto conv_issue = [&](int g2) {
        if ((g2 & 7) == 0) {
            const int p = g2 >> 3;
            const float* xb = x + (size_t)(m0 + wid * 16) * 42 + (p >> 2) * 7 + (p & 3);
            xhi[0] = f2h2(xb[(size_t)g * 42 + xo0],       xb[(size_t)g * 42 + xo0 + 1]);
            xhi[1] = f2h2(xb[(size_t)(g + 8) * 42 + xo0], xb[(size_t)(g + 8) * 42 + xo0 + 1]);
            xhi[2] = f2h2(xb[(size_t)g * 42 + xo1],       xb[(size_t)g * 42 + xo1 + 1]);
            xhi[3] = f2h2(xb[(size_t)(g + 8) * 42 + xo1], xb[(size_t)(g + 8) * 42 + xo1 + 1]);
        }
        const int bg = (g2 & 7) * 4;
        uint32_t w0[4], w1[4];
        uint32_t wo0 = (uint32_t)b_kl * 512 + ((((uint32_t)(bg + b_ng)) ^ key) << 4);
        uint32_t wo1 = (uint32_t)b_kl * 512 + ((((uint32_t)(bg + 2 + b_ng)) ^ key) << 4);
        ldsm_x4t(w0, pool_u + OFF_WC + wo0);
        ldsm_x4t(w1, pool_u + OFF_WC + wo1);
#pragma unroll
        for (int nt = 0; nt < 4; nt++)
#pragma unroll
            for (int q = 0; q < 4; q++) cd[nt][q] = 0.f;
        mma16816(cd[0][0], cd[0][1], cd[0][2], cd[0][3],
                 xhi[0], xhi[1], xhi[2], xhi[3], w0[0], w0[1]);
        mma16816(cd[1][0], cd[1][1], cd[1][2], cd[1][3],
                 xhi[0], xhi[1], xhi[2], xhi[3], w0[2], w0[3]);
        mma16816(cd[2][0], cd[2][1], cd[2][2], cd[2][3],
                 xhi[0], xhi[1], xhi[2], xhi[3], w1[0], w1[1]);
        mma16816(cd[3][0], cd[3][1], cd[3][2], cd[3][3],
                 xhi[0], xhi[1], xhi[2], xhi[3], w1[2], w1[3]);
    };

    // ---- prime the pipeline: conv(group 0) ----
    conv_issue(0);

    // ================= main loop =================
#pragma unroll 1
    for (int it = 0; it < NITER; it++) {
        CP_WAIT1();
        __syncthreads();   // B[it%3] arrived & visible

        if (it + 2 < NITER) {
            const uint32_t sb = pool_u + OFF_B + ((it + 2) % 3) * 16384;
            const size_t kofs = (size_t)(it + 2) * 64 * 128;
#pragma unroll
            for (int j = 0; j < 4; j++)
                CP_ASYNC16(sb + oBs[j], gB + kofs + j * 8);
        }
        CP_COMMIT();

        const uint32_t sbB = pool_u + OFF_B + (it % 3) * 16384;

#pragma unroll
        for (int gg = 0; gg < 2; gg++) {
            const int gi  = it * 2 + gg;     // global group 0..95
            const int grp = gi & 7;

            // ---- 1. pack(gi): cd -> afr ----
            uint32_t afr[2][4];
#pragma unroll
            for (int pr = 0; pr < 2; pr++) {
                const float* t0 = cd[pr * 2];
                const float* t1 = cd[pr * 2 + 1];
                float2 s0 = *(const float2*)&shiftS[grp * 32 + pr * 16 + t2];
                float2 s1 = *(const float2*)&shiftS[grp * 32 + pr * 16 + 8 + t2];
                afr[pr][0] = f2h2(fmaxf(t0[0] + s0.x, 0.f), fmaxf(t0[1] + s0.y, 0.f));
                afr[pr][1] = f2h2(fmaxf(t0[2] + s0.x, 0.f), fmaxf(t0[3] + s0.y, 0.f));
                afr[pr][2] = f2h2(fmaxf(t1[0] + s1.x, 0.f), fmaxf(t1[1] + s1.y, 0.f));
                afr[pr][3] = f2h2(fmaxf(t1[2] + s1.x, 0.f), fmaxf(t1[3] + s1.y, 0.f));
            }

            // ---- 2. conv(gi+1) issued ahead (results mature under fc1) ----
            if (gi + 1 < 96) conv_issue(gi + 1);

            // ---- 3. fc1(gi): 2 k16 chunks x (4 x (2 LDSM + 4 MMA)) ----
#pragma unroll
            for (int pr = 0; pr < 2; pr++) {
                const uint32_t* af = afr[pr];
                const uint32_t kbase = sbB + (uint32_t)((gg * 2 + pr) * 16 + b_kl) * 256;
#pragma unroll
                for (int h = 0; h < 4; h++) {
                    uint32_t bA[4], bB[4];
                    uint32_t offA = ((((uint32_t)((h * 2 + 0) * 2 + b_ng)) ^ key) << 4);
                    uint32_t offB = ((((uint32_t)((h * 2 + 1) * 2 + b_ng)) ^ key) << 4);
                    ldsm_x4t(bA, kbase + offA);
                    ldsm_x4t(bB, kbase + offB);
                    const int n0 = h * 4;
                    mma16816(d[n0][0], d[n0][1], d[n0][2], d[n0][3],
                             af[0], af[1], af[2], af[3], bA[0], bA[1]);
                    mma16816(d[n0 + 1][0], d[n0 + 1][1], d[n0 + 1][2], d[n0 + 1][3],
                             af[0], af[1], af[2], af[3], bA[2], bA[3]);
                    mma16816(d[n0 + 2][0], d[n0 + 2][1], d[n0 + 2][2], d[n0 + 2][3],
                             af[0], af[1], af[2], af[3], bB[0], bB[1]);
                    mma16816(d[n0 + 3][0], d[n0 + 3][1], d[n0 + 3][2], d[n0 + 3][3],
                             af[0], af[1], af[2], af[3], bB[2], bB[3]);
                }
            }
        }
    }

    CP_WAIT0();
    __syncthreads();

    // ---------------- epilogue ----------------
    float* h1 = (float*)poolA;              // [128][129]
    float* h2 = (float*)(poolA + 66560);    // [128][65]

    {
        const int m = wid * 16 + g;
#pragma unroll
        for (int nt = 0; nt < 16; nt++) {
            int n = nt * 8 + t2;
            h1[m * 129 + n]           = fmaxf(d[nt][0] + biasS[n], 0.f);
            h1[m * 129 + n + 1]       = fmaxf(d[nt][1] + biasS[n + 1], 0.f);
            h1[(m + 8) * 129 + n]     = fmaxf(d[nt][2] + biasS[n], 0.f);
            h1[(m + 8) * 129 + n + 1] = fmaxf(d[nt][3] + biasS[n + 1], 0.f);
        }
    }
    __syncthreads();

    // layer2
#pragma unroll 1
    for (int it = 0; it < 32; it++) {
        int idx = it * 256 + tid;
        int bd = idx >> 6, o = idx & 63;
        int oo = o & 31;
        const float* h1b  = h1 + bd * 129 + ((o < 32) ? 0 : 64);
        const float* wmat = (o < 32) ? pw2 : vw2;
        float s = (o < 32) ? pb2[oo] : vb2[oo];
#pragma unroll 8
        for (int k = 0; k < 64; k++) s += h1b[k] * wmat[k * 32 + oo];
        h2[bd * 65 + o] = fmaxf(s, 0.f);
    }
    __syncthreads();

    // layer3 + softmax / tanh
    if (tid < 128) {
        int gb = m0 + tid;
        const float* hp = h2 + tid * 65;
        float lg[7];
#pragma unroll
        for (int j = 0; j < 7; j++) {
            float s = pb3[j];
#pragma unroll
            for (int k = 0; k < 32; k++) s += hp[k] * pw3[k * 7 + j];
            lg[j] = s;
        }
        float mx = lg[0];
#pragma unroll
        for (int j = 1; j < 7; j++) mx = fmaxf(mx, lg[j]);
        float se = 0.f;
#pragma unroll
        for (int j = 0; j < 7; j++) { lg[j] = expf(lg[j] - mx); se += lg[j]; }
        float inv = 1.f / se;
#pragma unroll
        for (int j = 0; j < 7; j++) out[(size_t)gb * 7 + j] = lg[j] * inv;

        float v = vb3[0];
#pragma unroll
        for (int k = 0; k < 32; k++) v += hp[32 + k] * vw3[k];
        out[(size_t)BATCH * 7 + gb] = tanhf(v);
    }
}

// =========================================================================
extern "C" void kernel_launch(void* const* d_in, const int* in_sizes, int n_in,
                              void* d_out, int out_size)
{
    const float* x        = (const float*)d_in[0];
    const float* conv_w   = (const float*)d_in[1];
    /* conv_b cancels through batch-norm */
    const float* bn_gamma = (const float*)d_in[3];
    const float* bn_beta  = (const float*)d_in[4];
    const float* pw1 = (const float*)d_in[5];
    const float* pb1 = (const float*)d_in[6];
    const float* pw2 = (const float*)d_in[7];
    const float* pb2 = (const float*)d_in[8];
    const float* pw3 = (const float*)d_in[9];
    const float* pb3 = (const float*)d_in[10];
    const float* vw1 = (const float*)d_in[11];
    const float* vb1 = (const float*)d_in[12];
    const float* vw2 = (const float*)d_in[13];
    const float* vb2 = (const float*)d_in[14];
    const float* vw3 = (const float*)d_in[15];
    const float* vb3 = (const float*)d_in[16];
    float* out = (float*)d_out;

    cudaFuncSetAttribute(k_fused, cudaFuncAttributeMaxDynamicSharedMemorySize, SMEM_DYN);

    k_moments<<<NBLK_MOM, 256>>>(x);
    k_finalize<<<1, 256>>>(conv_w, bn_gamma, bn_beta);
    k_prep<<<FLAT, 128>>>(pw1, vw1);
    k_fused<<<BATCH / 128, 256, SMEM_DYN>>>(x, pb1, vb1, pw2, pb2, pw3, pb3,
                                            vw2, vb2, vw3, vb3, out);
}